// round 16
// baseline (speedup 1.0000x reference)
#include <cuda_runtime.h>
#include <cuda_fp16.h>
#include <math.h>

// ---------------------------------------------------------------------------
// Swin block, B=4 C=96 H=W=256 WS=8 NH=4 HD=24 SHIFT=4 N=64 MLP_H=384
// Fully fused per-window kernel (LN1+QKV+attn+proj+res+LN2+MLP+res -> NCHW).
// fp16 mma m16n8k16, fp32 accum, 256-thr CTAs, 2 CTAs/SM.
// R16 vs R15: (1) MLP software-pipelined with double-buffered hct —
// fc1(ng+1) overlaps fc2(ng) in one barrier interval (barriers 7->5);
// (2) softmax max-subtraction removed (scores tiny, mask = -100 -> exp->0).
// ---------------------------------------------------------------------------

typedef unsigned uu;

__device__ __forceinline__ uu packh2(float lo, float hi) {
    __half2 h = __floats2half2_rn(lo, hi);
    return *reinterpret_cast<uu*>(&h);
}
__device__ __forceinline__ float2 h2f2(uu u) {
    __half2 h = *reinterpret_cast<__half2*>(&u);
    return __half22float2(h);
}
__device__ __forceinline__ void mmaf16(float* d, const uu* a, uu b0, uu b1) {
    asm("mma.sync.aligned.m16n8k16.row.col.f32.f16.f16.f32 "
        "{%0,%1,%2,%3},{%4,%5,%6,%7},{%8,%9},{%0,%1,%2,%3};"
        : "+f"(d[0]), "+f"(d[1]), "+f"(d[2]), "+f"(d[3])
        : "r"(a[0]), "r"(a[1]), "r"(a[2]), "r"(a[3]), "r"(b0), "r"(b1));
}
// 2-kstep permutation: pair p -> slot; lane (lq,lr) reads uint4 at group*16+lr*4
__device__ __forceinline__ int pperm2(int p) {
    return (p & ~15) | ((p & 3) << 2) | (((p >> 3) & 1) << 1) | ((p >> 2) & 1);
}

// Abramowitz-Stegun 7.1.26 erf (|abs err| < 1.5e-7)
__device__ __forceinline__ float erf_as(float x) {
    float ax = fabsf(x);
    float t  = __frcp_rn(1.f + 0.3275911f * ax);
    float y  = t * (0.254829592f + t * (-0.284496736f + t * (1.421413741f
             + t * (-1.453152027f + t * 1.061405429f))));
    float r  = 1.f - y * __expf(-ax * ax);
    return copysignf(r, x);
}

// half weight images, pperm2-permuted pairs (uint4 = 2 k-steps per lane)
__device__ uu g_wqkv[288 * 48];   // q-rows (0..95) pre-scaled by 24^-0.5
__device__ uu g_wproj[96 * 48];
__device__ uu g_w1[384 * 48];
__device__ uu g_w2[96 * 192];
__device__ float g_bqkv[288];
// bias+mask table, half2-packed, lane-contiguous: [v][h][n][lr*8 + nt]
__device__ uu g_sbias[4 * 4 * 64 * 32];

__global__ void swin_prep_kernel(const float* __restrict__ qkv_w,
                                 const float* __restrict__ proj_w,
                                 const float* __restrict__ fc1_w,
                                 const float* __restrict__ fc2_w,
                                 const float* __restrict__ qkv_b,
                                 const float* __restrict__ rpb)
{
    const float scale = 0.2041241452319315f;  // 24^-0.5
    int t = blockIdx.x * blockDim.x + threadIdx.x;
    int T = gridDim.x * blockDim.x;
    for (int i = t; i < 288 * 48; i += T) {
        int r = i / 48, p = i - r * 48;
        float s = (r < 96) ? scale : 1.f;
        g_wqkv[r * 48 + pperm2(p)] =
            packh2(__ldg(qkv_w + r * 96 + 2 * p) * s,
                   __ldg(qkv_w + r * 96 + 2 * p + 1) * s);
    }
    for (int i = t; i < 288; i += T)
        g_bqkv[i] = __ldg(qkv_b + i) * ((i < 96) ? scale : 1.f);
    for (int i = t; i < 96 * 48; i += T) {
        int r = i / 48, p = i - r * 48;
        g_wproj[r * 48 + pperm2(p)] =
            packh2(__ldg(proj_w + r * 96 + 2 * p), __ldg(proj_w + r * 96 + 2 * p + 1));
    }
    for (int i = t; i < 384 * 48; i += T) {
        int r = i / 48, p = i - r * 48;
        g_w1[r * 48 + pperm2(p)] =
            packh2(__ldg(fc1_w + r * 96 + 2 * p), __ldg(fc1_w + r * 96 + 2 * p + 1));
    }
    for (int i = t; i < 96 * 192; i += T) {
        int c = i / 192, p = i - c * 192;
        g_w2[c * 192 + pperm2(p)] =
            packh2(__ldg(fc2_w + c * 384 + 2 * p), __ldg(fc2_w + c * 384 + 2 * p + 1));
    }
    // bias+mask, half2 packed: word w = lr*8 + nt holds m pair (nt*8+2lr, +1)
    for (int i = t; i < 4 * 4 * 64 * 32; i += T) {
        int w  = i & 31;
        int lr = w >> 3, nt = w & 7;
        int n  = (i >> 5) & 63;
        int h  = (i >> 11) & 3;
        int v  = (i >> 13) & 3;
        int i1 = n >> 3, j1 = n & 7;
        float bv[2];
        #pragma unroll
        for (int par = 0; par < 2; par++) {
            int m  = nt * 8 + 2 * lr + par;
            int i2 = m >> 3, j2 = m & 7;
            int ridx = (i1 - i2 + 7) * 15 + (j1 - j2 + 7);
            float bias = __ldg(rpb + ridx * 4 + h);
            int rn = (v & 2) ? ((i1 < 4) ? 1 : 2) : 0;
            int cn = (v & 1) ? ((j1 < 4) ? 1 : 2) : 0;
            int rm = (v & 2) ? ((i2 < 4) ? 1 : 2) : 0;
            int cm = (v & 1) ? ((j2 < 4) ? 1 : 2) : 0;
            if ((rn * 3 + cn) != (rm * 3 + cm)) bias -= 100.f;
            bv[par] = bias;
        }
        g_sbias[i] = packh2(bv[0], bv[1]);
    }
}

// ---------------- fused kernel smem (word indices) ----------------
#define F_XT   0        // raw x fp32 [64][104] -> ys f16 [64][48]
#define F_XH   6656     // Xh f16 [64][48] -> AO -> hct buf0 (3072 words)
#define F_Q    9728     // Q f16 [4][64][16] (4096) -> hout fp32 [64][104]
#define F_K    13824    // K f16 [4][64][16] (4096)
#define F_VT   17920    // V^T f16 [2][96][16] (3072)
#define F_HC1  20992    // hct buf1 (3072)
#define F_TOT  24064    // 96,256 bytes

__global__ void __launch_bounds__(256, 2) swin_fused_kernel(
    const float* __restrict__ x,
    const float* __restrict__ norm_w, const float* __restrict__ norm_b,
    const float* __restrict__ proj_b,
    const float* __restrict__ n2w, const float* __restrict__ n2b,
    const float* __restrict__ b1g, const float* __restrict__ b2g,
    float* __restrict__ out)
{
    extern __shared__ float sm[];
    float* xt   = sm + F_XT;
    float* hout = sm + F_Q;             // h = x + attn (overlays Q..K)

    uu* Xhu = (uu*)(sm + F_XH);
    uu* AOu = (uu*)(sm + F_XH);
    uu* Hc0 = (uu*)(sm + F_XH);         // hct buffer 0 (overlays AO after proj)
    uu* Hc1 = (uu*)(sm + F_HC1);        // hct buffer 1
    uu* Ysu = (uu*)(sm + F_XT);
    uu* Qu  = (uu*)(sm + F_Q);
    uu* Ku  = (uu*)(sm + F_K);
    uu* Vtu = (uu*)(sm + F_VT);

    const int tid  = threadIdx.x;
    const int lane = tid & 31;
    const int wid  = tid >> 5;            // 0..7
    const int lq   = lane >> 2;
    const int lr   = lane & 3;
    const int mh   = wid >> 2;            // 0..1 (m32 group)
    const int nq   = wid & 3;             // 0..3
    const int hh   = wid & 3;             // scores/AV head
    const int mq   = wid >> 2;            // scores/AV 32-row slice
    const int blk  = blockIdx.x;
    const int b    = blk >> 10;
    const int wh   = (blk >> 5) & 31;
    const int ww   = blk & 31;
    const int variant = ((wh == 31) ? 2 : 0) | ((ww == 31) ? 1 : 0);

    // zero Q/K pad slots (disjoint from QKV-epilogue writes; ordered by (3))
    for (int i = tid; i < 2048; i += 256) {
        int sl = 3 + 4 * (i & 3);
        int hd = (i >> 2) & 3;
        int r  = (i >> 4) & 63;
        uu* dst = (i & 1024) ? Ku : Qu;
        dst[hd * 1024 + r * 16 + sl] = 0;
    }

    const int xbase = b * 96 * 65536;

    // ---- gather + LN1 in registers (4 lanes per token), pos inlined ----
    {
        int p = tid >> 2, part = tid & 3;
        int pr = (wh * 8 + (p >> 3) + 4) & 255;
        int pc = (ww * 8 + (p & 7) + 4) & 255;
        const float* xp = x + xbase + pr * 256 + pc;
        float g[24];
        #pragma unroll
        for (int i = 0; i < 24; i++) g[i] = __ldg(xp + ((part * 24 + i) << 16));
        float s = 0.f, s2 = 0.f;
        #pragma unroll
        for (int i = 0; i < 24; i++) { s += g[i]; s2 += g[i] * g[i]; }
        #pragma unroll
        for (int o = 1; o < 4; o <<= 1) {
            s  += __shfl_xor_sync(0xffffffffu, s,  o);
            s2 += __shfl_xor_sync(0xffffffffu, s2, o);
        }
        float mu = s * (1.f / 96.f);
        float var = s2 * (1.f / 96.f) - mu * mu;
        float rs = rsqrtf(var + 1e-6f);
        float* xr = xt + p * 104 + part * 24;
        #pragma unroll
        for (int i = 0; i < 6; i++)
            *(float4*)(xr + 4 * i) = make_float4(g[4 * i], g[4 * i + 1],
                                                 g[4 * i + 2], g[4 * i + 3]);
        #pragma unroll
        for (int i = 0; i < 12; i++) {
            int c = part * 24 + 2 * i;
            float2 nw = __ldg((const float2*)norm_w + (c >> 1));
            float2 nb = __ldg((const float2*)norm_b + (c >> 1));
            Xhu[p * 48 + pperm2(part * 12 + i)] =
                packh2((g[2 * i] - mu) * rs * nw.x + nb.x,
                       (g[2 * i + 1] - mu) * rs * nw.y + nb.y);
        }
    }
    __syncthreads();                                   // (2)

    // -------- QKV: m32 x n72, 3 ks2 groups (2 k-steps each) --------
    {
        float acc[9][2][4];
        #pragma unroll
        for (int nt = 0; nt < 9; nt++)
            #pragma unroll
            for (int mt = 0; mt < 2; mt++)
                #pragma unroll
                for (int e = 0; e < 4; e++) acc[nt][mt][e] = 0.f;

        const uu* wb = g_wqkv + (nq * 72 + lq) * 48 + lr * 4;
        #pragma unroll
        for (int ks2 = 0; ks2 < 3; ks2++) {
            uu ae[2][4], ao[2][4];
            #pragma unroll
            for (int mt = 0; mt < 2; mt++) {
                uint4 lo = *(const uint4*)(Xhu + (mh * 32 + mt * 16 + lq) * 48
                                           + ks2 * 16 + lr * 4);
                uint4 hi = *(const uint4*)(Xhu + (mh * 32 + mt * 16 + lq + 8) * 48
                                           + ks2 * 16 + lr * 4);
                ae[mt][0] = lo.x; ae[mt][1] = hi.x; ae[mt][2] = lo.y; ae[mt][3] = hi.y;
                ao[mt][0] = lo.z; ao[mt][1] = hi.z; ao[mt][2] = lo.w; ao[mt][3] = hi.w;
            }
            #pragma unroll
            for (int nt = 0; nt < 9; nt++) {
                uint4 bw = __ldg((const uint4*)(wb + nt * 8 * 48 + ks2 * 16));
                #pragma unroll
                for (int mt = 0; mt < 2; mt++) {
                    mmaf16(acc[nt][mt], ae[mt], bw.x, bw.y);
                    mmaf16(acc[nt][mt], ao[mt], bw.z, bw.w);
                }
            }
        }
        #pragma unroll
        for (int nt = 0; nt < 9; nt++) {
            int j0 = nq * 72 + nt * 8;
            float bl = __ldg(g_bqkv + j0 + 2 * lr);
            float bh = __ldg(g_bqkv + j0 + 2 * lr + 1);
            #pragma unroll
            for (int mt = 0; mt < 2; mt++) {
                int row = mh * 32 + mt * 16 + lq;
                int col = j0 + 2 * lr;
                float v0 = acc[nt][mt][0] + bl;
                float v1 = acc[nt][mt][1] + bh;
                float v2 = acc[nt][mt][2] + bl;
                float v3 = acc[nt][mt][3] + bh;
                if (col < 192) {
                    uu* dst;
                    int cl = col;
                    if (col < 96) { dst = Qu; } else { dst = Ku; cl = col - 96; }
                    int head = cl / 24;
                    int q    = (cl - head * 24) >> 1;
                    int sl   = ((q & 3) << 2) | (((q >> 3) & 1) << 1) | ((q >> 2) & 1);
                    dst[head * 1024 + row * 16 + sl]       = packh2(v0, v1);
                    dst[head * 1024 + (row + 8) * 16 + sl] = packh2(v2, v3);
                } else {
                    int cc = col - 192;
                    #pragma unroll
                    for (int e = 0; e < 4; e++) {
                        float v = (e == 0) ? v0 : (e == 1) ? v1 : (e == 2) ? v2 : v3;
                        int n = row + ((e >> 1) << 3);
                        int c2 = cc + (e & 1);
                        int tp = n >> 1;
                        int g  = tp >> 4;
                        int q  = tp & 15;
                        int sl = ((q & 3) << 2) | (((q >> 3) & 1) << 1) | ((q >> 2) & 1);
                        ((__half*)(Vtu + g * 1536 + c2 * 16 + sl))[n & 1] =
                            __float2half_rn(v);
                    }
                }
            }
        }
    }
    __syncthreads();                                   // (3)

    // ---- Scores (m32 x 64): acc init from half2 g_sbias, softmax, AV ----
    {
        float acc[8][2][4];
        const uu* sb = g_sbias + (((variant * 4 + hh) * 64 + mq * 32 + lq) * 32)
                     + lr * 8;
        #pragma unroll
        for (int mt = 0; mt < 2; mt++) {
            const uint4* lo4 = (const uint4*)(sb + (mt * 16) * 32);
            const uint4* hi4 = (const uint4*)(sb + (mt * 16 + 8) * 32);
            #pragma unroll
            for (int q = 0; q < 2; q++) {
                uint4 L = __ldg(lo4 + q);
                uint4 H = __ldg(hi4 + q);
                float2 f;
                f = h2f2(L.x); acc[4*q+0][mt][0] = f.x; acc[4*q+0][mt][1] = f.y;
                f = h2f2(L.y); acc[4*q+1][mt][0] = f.x; acc[4*q+1][mt][1] = f.y;
                f = h2f2(L.z); acc[4*q+2][mt][0] = f.x; acc[4*q+2][mt][1] = f.y;
                f = h2f2(L.w); acc[4*q+3][mt][0] = f.x; acc[4*q+3][mt][1] = f.y;
                f = h2f2(H.x); acc[4*q+0][mt][2] = f.x; acc[4*q+0][mt][3] = f.y;
                f = h2f2(H.y); acc[4*q+1][mt][2] = f.x; acc[4*q+1][mt][3] = f.y;
                f = h2f2(H.z); acc[4*q+2][mt][2] = f.x; acc[4*q+2][mt][3] = f.y;
                f = h2f2(H.w); acc[4*q+3][mt][2] = f.x; acc[4*q+3][mt][3] = f.y;
            }
        }
        {
            uu ae[2][4], ao[2][4];
            #pragma unroll
            for (int mt = 0; mt < 2; mt++) {
                uint4 lo = *(const uint4*)(Qu + hh * 1024
                                           + (mq * 32 + mt * 16 + lq) * 16 + lr * 4);
                uint4 hi = *(const uint4*)(Qu + hh * 1024
                                           + (mq * 32 + mt * 16 + lq + 8) * 16 + lr * 4);
                ae[mt][0] = lo.x; ae[mt][1] = hi.x; ae[mt][2] = lo.y; ae[mt][3] = hi.y;
                ao[mt][0] = lo.z; ao[mt][1] = hi.z; ao[mt][2] = lo.w; ao[mt][3] = hi.w;
            }
            #pragma unroll
            for (int nt = 0; nt < 8; nt++) {
                uint4 kf = *(const uint4*)(Ku + hh * 1024 + (nt * 8 + lq) * 16 + lr * 4);
                #pragma unroll
                for (int mt = 0; mt < 2; mt++) {
                    mmaf16(acc[nt][mt], ae[mt], kf.x, kf.y);
                    mmaf16(acc[nt][mt], ao[mt], kf.z, kf.w);
                }
            }
        }
        // softmax (no max-subtract: scores tiny, mask = -100 -> exp -> 0) + AV
        float fav[3][2][4];
        #pragma unroll
        for (int nt = 0; nt < 3; nt++)
            #pragma unroll
            for (int mt = 0; mt < 2; mt++)
                #pragma unroll
                for (int e = 0; e < 4; e++) fav[nt][mt][e] = 0.f;

        #pragma unroll
        for (int mt = 0; mt < 2; mt++) {
            float sm0 = 0.f, sm1 = 0.f;
            #pragma unroll
            for (int nt = 0; nt < 8; nt++) {
                acc[nt][mt][0] = __expf(acc[nt][mt][0]);
                acc[nt][mt][1] = __expf(acc[nt][mt][1]);
                acc[nt][mt][2] = __expf(acc[nt][mt][2]);
                acc[nt][mt][3] = __expf(acc[nt][mt][3]);
                sm0 += acc[nt][mt][0] + acc[nt][mt][1];
                sm1 += acc[nt][mt][2] + acc[nt][mt][3];
            }
            #pragma unroll
            for (int o = 1; o < 4; o <<= 1) {
                sm0 += __shfl_xor_sync(0xffffffffu, sm0, o);
                sm1 += __shfl_xor_sync(0xffffffffu, sm1, o);
            }
            float inv0 = __fdividef(1.f, sm0);
            float inv1 = __fdividef(1.f, sm1);
            #pragma unroll
            for (int g = 0; g < 2; g++) {
                uu a_e[4], a_o[4];
                a_e[0] = packh2(acc[4 * g][mt][0] * inv0,     acc[4 * g][mt][1] * inv0);
                a_e[1] = packh2(acc[4 * g][mt][2] * inv1,     acc[4 * g][mt][3] * inv1);
                a_e[2] = packh2(acc[4 * g + 1][mt][0] * inv0, acc[4 * g + 1][mt][1] * inv0);
                a_e[3] = packh2(acc[4 * g + 1][mt][2] * inv1, acc[4 * g + 1][mt][3] * inv1);
                a_o[0] = packh2(acc[4 * g + 2][mt][0] * inv0, acc[4 * g + 2][mt][1] * inv0);
                a_o[1] = packh2(acc[4 * g + 2][mt][2] * inv1, acc[4 * g + 2][mt][3] * inv1);
                a_o[2] = packh2(acc[4 * g + 3][mt][0] * inv0, acc[4 * g + 3][mt][1] * inv0);
                a_o[3] = packh2(acc[4 * g + 3][mt][2] * inv1, acc[4 * g + 3][mt][3] * inv1);
                #pragma unroll
                for (int nt = 0; nt < 3; nt++) {
                    uint4 vf = *(const uint4*)(Vtu + g * 1536
                                               + (hh * 24 + nt * 8 + lq) * 16 + lr * 4);
                    mmaf16(fav[nt][mt], a_e, vf.x, vf.y);
                    mmaf16(fav[nt][mt], a_o, vf.z, vf.w);
                }
            }
        }
        // AO overlay of Xh safe without barrier (Xh last read before (3))
        #pragma unroll
        for (int nt = 0; nt < 3; nt++)
            #pragma unroll
            for (int mt = 0; mt < 2; mt++) {
                int n0 = mq * 32 + mt * 16 + lq;
                int cp = hh * 12 + nt * 4 + lr;
                AOu[n0 * 48 + pperm2(cp)]       = packh2(fav[nt][mt][0], fav[nt][mt][1]);
                AOu[(n0 + 8) * 48 + pperm2(cp)] = packh2(fav[nt][mt][2], fav[nt][mt][3]);
            }
    }
    __syncthreads();                                   // (5)

    // ------- Proj (m32 x n24, 3 ks2) + residual(xt) -> hout -------
    {
        float acc[3][2][4];
        #pragma unroll
        for (int nt = 0; nt < 3; nt++)
            #pragma unroll
            for (int mt = 0; mt < 2; mt++)
                #pragma unroll
                for (int e = 0; e < 4; e++) acc[nt][mt][e] = 0.f;

        const uu* wb = g_wproj + (nq * 24 + lq) * 48 + lr * 4;
        #pragma unroll
        for (int ks2 = 0; ks2 < 3; ks2++) {
            uu ae[2][4], ao[2][4];
            #pragma unroll
            for (int mt = 0; mt < 2; mt++) {
                uint4 lo = *(const uint4*)(AOu + (mh * 32 + mt * 16 + lq) * 48
                                           + ks2 * 16 + lr * 4);
                uint4 hi = *(const uint4*)(AOu + (mh * 32 + mt * 16 + lq + 8) * 48
                                           + ks2 * 16 + lr * 4);
                ae[mt][0] = lo.x; ae[mt][1] = hi.x; ae[mt][2] = lo.y; ae[mt][3] = hi.y;
                ao[mt][0] = lo.z; ao[mt][1] = hi.z; ao[mt][2] = lo.w; ao[mt][3] = hi.w;
            }
            #pragma unroll
            for (int nt = 0; nt < 3; nt++) {
                uint4 bw = __ldg((const uint4*)(wb + nt * 8 * 48 + ks2 * 16));
                #pragma unroll
                for (int mt = 0; mt < 2; mt++) {
                    mmaf16(acc[nt][mt], ae[mt], bw.x, bw.y);
                    mmaf16(acc[nt][mt], ao[mt], bw.z, bw.w);
                }
            }
        }
        #pragma unroll
        for (int nt = 0; nt < 3; nt++) {
            int j0 = nq * 24 + nt * 8;
            float bl = __ldg(proj_b + j0 + 2 * lr);
            float bh = __ldg(proj_b + j0 + 2 * lr + 1);
            #pragma unroll
            for (int mt = 0; mt < 2; mt++)
                #pragma unroll
                for (int e = 0; e < 4; e++) {
                    int n = mh * 32 + mt * 16 + lq + ((e >> 1) << 3);
                    int j = j0 + 2 * lr + (e & 1);
                    hout[n * 104 + j] = acc[nt][mt][e] + ((e & 1) ? bh : bl)
                                      + xt[n * 104 + j];
                }
        }
    }
    __syncthreads();                                   // (6)

    // ---- LN2 from hout -> ys f16 (overlays xt region) ----
    {
        int p = tid >> 2, part = tid & 3;
        float g[24];
        const float* hp = hout + p * 104 + part * 24;
        #pragma unroll
        for (int i = 0; i < 6; i++) {
            float4 v = *(const float4*)(hp + 4 * i);
            g[4 * i] = v.x; g[4 * i + 1] = v.y; g[4 * i + 2] = v.z; g[4 * i + 3] = v.w;
        }
        float s = 0.f, s2 = 0.f;
        #pragma unroll
        for (int i = 0; i < 24; i++) { s += g[i]; s2 += g[i] * g[i]; }
        #pragma unroll
        for (int o = 1; o < 4; o <<= 1) {
            s  += __shfl_xor_sync(0xffffffffu, s,  o);
            s2 += __shfl_xor_sync(0xffffffffu, s2, o);
        }
        float mu = s * (1.f / 96.f);
        float var = s2 * (1.f / 96.f) - mu * mu;
        float rs = rsqrtf(var + 1e-6f);
        #pragma unroll
        for (int i = 0; i < 12; i++) {
            int c = part * 24 + 2 * i;
            float2 nw = __ldg((const float2*)n2w + (c >> 1));
            float2 nb = __ldg((const float2*)n2b + (c >> 1));
            Ysu[p * 48 + pperm2(part * 12 + i)] =
                packh2((g[2 * i] - mu) * rs * nw.x + nb.x,
                       (g[2 * i + 1] - mu) * rs * nw.y + nb.y);
        }
    }
    __syncthreads();                                   // (7)

    // ---- MLP: Ys A-fragments in registers; double-buffered hct pipeline ----
    uu yse[3][2][4], yso[3][2][4];
    #pragma unroll
    for (int ks2 = 0; ks2 < 3; ks2++)
        #pragma unroll
        for (int mt = 0; mt < 2; mt++) {
            uint4 lo = *(const uint4*)(Ysu + (mh * 32 + mt * 16 + lq) * 48
                                       + ks2 * 16 + lr * 4);
            uint4 hi = *(const uint4*)(Ysu + (mh * 32 + mt * 16 + lq + 8) * 48
                                       + ks2 * 16 + lr * 4);
            yse[ks2][mt][0] = lo.x; yse[ks2][mt][1] = hi.x;
            yse[ks2][mt][2] = lo.y; yse[ks2][mt][3] = hi.y;
            yso[ks2][mt][0] = lo.z; yso[ks2][mt][1] = hi.z;
            yso[ks2][mt][2] = lo.w; yso[ks2][mt][3] = hi.w;
        }

    // fc1 for hidden quarter ng -> Hc buffer
    auto fc1_quarter = [&](int ng, uu* Hc) {
        float acc1[3][2][4];
        #pragma unroll
        for (int nt = 0; nt < 3; nt++)
            #pragma unroll
            for (int mt = 0; mt < 2; mt++)
                #pragma unroll
                for (int e = 0; e < 4; e++) acc1[nt][mt][e] = 0.f;

        const uu* wb = g_w1 + (ng * 96 + nq * 24 + lq) * 48 + lr * 4;
        #pragma unroll
        for (int ks2 = 0; ks2 < 3; ks2++) {
            #pragma unroll
            for (int nt = 0; nt < 3; nt++) {
                uint4 bw = __ldg((const uint4*)(wb + nt * 8 * 48 + ks2 * 16));
                #pragma unroll
                for (int mt = 0; mt < 2; mt++) {
                    mmaf16(acc1[nt][mt], yse[ks2][mt], bw.x, bw.y);
                    mmaf16(acc1[nt][mt], yso[ks2][mt], bw.z, bw.w);
                }
            }
        }
        #pragma unroll
        for (int nt = 0; nt < 3; nt++) {
            int jl = nq * 24 + nt * 8;
            float bl = __ldg(b1g + ng * 96 + jl + 2 * lr);
            float bh = __ldg(b1g + ng * 96 + jl + 2 * lr + 1);
            int pl = (jl >> 1) + lr;                   // local hidden pair 0..47
            #pragma unroll
            for (int mt = 0; mt < 2; mt++) {
                int p0r = mh * 32 + mt * 16 + lq;
                float v0 = acc1[nt][mt][0] + bl;
                float v1 = acc1[nt][mt][1] + bh;
                float v2 = acc1[nt][mt][2] + bl;
                float v3 = acc1[nt][mt][3] + bh;
                v0 = 0.5f * v0 * (1.f + erf_as(v0 * 0.7071067811865475f));
                v1 = 0.5f * v1 * (1.f + erf_as(v1 * 0.7071067811865475f));
                v2 = 0.5f * v2 * (1.f + erf_as(v2 * 0.7071067811865475f));
                v3 = 0.5f * v3 * (1.f + erf_as(v3 * 0.7071067811865475f));
                Hc[p0r * 48 + pperm2(pl)]       = packh2(v0, v1);
                Hc[(p0r + 8) * 48 + pperm2(pl)] = packh2(v2, v3);
            }
        }
    };

    float acc2[3][2][4];
    #pragma unroll
    for (int nt = 0; nt < 3; nt++)
        #pragma unroll
        for (int mt = 0; mt < 2; mt++)
            #pragma unroll
            for (int e = 0; e < 4; e++) acc2[nt][mt][e] = 0.f;

    fc1_quarter(0, Hc0);
    __syncthreads();                                   // buf0 ready

    #pragma unroll
    for (int ng = 0; ng < 4; ng++) {
        // overlap: fc1(ng+1) into the other buffer while fc2(ng) reads this one
        if (ng < 3) fc1_quarter(ng + 1, ((ng + 1) & 1) ? Hc1 : Hc0);

        uu* Hc = (ng & 1) ? Hc1 : Hc0;
        const uu* wb2 = g_w2 + (nq * 24 + lq) * 192 + ng * 48 + lr * 4;
        #pragma unroll
        for (int ks2 = 0; ks2 < 3; ks2++) {
            uu ae[2][4], ao[2][4];
            #pragma unroll
            for (int mt = 0; mt < 2; mt++) {
                uint4 lo = *(const uint4*)(Hc + (mh * 32 + mt * 16 + lq) * 48
                                           + ks2 * 16 + lr * 4);
                uint4 hi = *(const uint4*)(Hc + (mh * 32 + mt * 16 + lq + 8) * 48
                                           + ks2 * 16 + lr * 4);
                ae[mt][0] = lo.x; ae[mt][1] = hi.x; ae[mt][2] = lo.y; ae[mt][3] = hi.y;
                ao[mt][0] = lo.z; ao[mt][1] = hi.z; ao[mt][2] = lo.w; ao[mt][3] = hi.w;
            }
            #pragma unroll
            for (int nt = 0; nt < 3; nt++) {
                uint4 bw = __ldg((const uint4*)(wb2 + nt * 8 * 192 + ks2 * 16));
                #pragma unroll
                for (int mt = 0; mt < 2; mt++) {
                    mmaf16(acc2[nt][mt], ae[mt], bw.x, bw.y);
                    mmaf16(acc2[nt][mt], ao[mt], bw.z, bw.w);
                }
            }
        }
        if (ng < 3) __syncthreads();   // next fc2's RAW + next fc1's WAR
    }

    // epilogue: bias + residual (hout) -> DIRECT gmem store (32B sectors)
    #pragma unroll
    for (int nt = 0; nt < 3; nt++) {
        int c0 = nq * 24 + nt * 8;
        float bl = __ldg(b2g + c0 + 2 * lr);
        float bh = __ldg(b2g + c0 + 2 * lr + 1);
        #pragma unroll
        for (int mt = 0; mt < 2; mt++)
            #pragma unroll
            for (int e = 0; e < 4; e++) {
                int p = mh * 32 + mt * 16 + lq + ((e >> 1) << 3);
                int c = c0 + 2 * lr + (e & 1);
                float v = acc2[nt][mt][e] + ((e & 1) ? bh : bl)
                        + hout[p * 104 + c];
                int pr = (wh * 8 + (p >> 3) + 4) & 255;
                int pc = (ww * 8 + (p & 7) + 4) & 255;
                out[((size_t)(b * 96 + c) << 16) + pr * 256 + pc] = v;
            }
    }
}

extern "C" void kernel_launch(void* const* d_in, const int* in_sizes, int n_in,
                              void* d_out, int out_size)
{
    const float* x      = (const float*)d_in[0];
    const float* norm_w = (const float*)d_in[1];
    const float* norm_b = (const float*)d_in[2];
    const float* qkv_w  = (const float*)d_in[3];
    const float* qkv_b  = (const float*)d_in[4];
    const float* proj_w = (const float*)d_in[5];
    const float* proj_b = (const float*)d_in[6];
    const float* rpb    = (const float*)d_in[7];
    const float* n2w    = (const float*)d_in[8];
    const float* n2b    = (const float*)d_in[9];
    const float* fc1_w  = (const float*)d_in[10];
    const float* fc1_b  = (const float*)d_in[11];
    const float* fc2_w  = (const float*)d_in[12];
    const float* fc2_b  = (const float*)d_in[13];
    float* out = (float*)d_out;

    cudaFuncSetAttribute(swin_fused_kernel, cudaFuncAttributeMaxDynamicSharedMemorySize,
                         F_TOT * 4);

    swin_prep_kernel<<<112, 256>>>(qkv_w, proj_w, fc1_w, fc2_w, qkv_b, rpb);
    swin_fused_kernel<<<4096, 256, F_TOT * 4>>>(
        x, norm_w, norm_b, proj_b, n2w, n2b, fc1_b, fc2_b, out);
}

// round 17
// speedup vs baseline: 1.0189x; 1.0189x over previous
#include <cuda_runtime.h>
#include <cuda_fp16.h>
#include <math.h>

// ---------------------------------------------------------------------------
// Swin block, B=4 C=96 H=W=256 WS=8 NH=4 HD=24 SHIFT=4 N=64 MLP_H=384
// Fully fused per-window kernel (LN1+QKV+attn+proj+res+LN2+MLP+res -> NCHW).
// fp16 mma m16n8k16, fp32 accum, 256-thr CTAs, 2 CTAs/SM.
// R17 = R15 (best, 454.7us) + ONLY the softmax max-subtraction removal
// (scores tiny after LN + 0.02-scale weights; mask -100 -> exp -> 0).
// ---------------------------------------------------------------------------

typedef unsigned uu;

__device__ __forceinline__ uu packh2(float lo, float hi) {
    __half2 h = __floats2half2_rn(lo, hi);
    return *reinterpret_cast<uu*>(&h);
}
__device__ __forceinline__ float2 h2f2(uu u) {
    __half2 h = *reinterpret_cast<__half2*>(&u);
    return __half22float2(h);
}
__device__ __forceinline__ void mmaf16(float* d, const uu* a, uu b0, uu b1) {
    asm("mma.sync.aligned.m16n8k16.row.col.f32.f16.f16.f32 "
        "{%0,%1,%2,%3},{%4,%5,%6,%7},{%8,%9},{%0,%1,%2,%3};"
        : "+f"(d[0]), "+f"(d[1]), "+f"(d[2]), "+f"(d[3])
        : "r"(a[0]), "r"(a[1]), "r"(a[2]), "r"(a[3]), "r"(b0), "r"(b1));
}
// 2-kstep permutation: pair p -> slot; lane (lq,lr) reads uint4 at group*16+lr*4
__device__ __forceinline__ int pperm2(int p) {
    return (p & ~15) | ((p & 3) << 2) | (((p >> 3) & 1) << 1) | ((p >> 2) & 1);
}

// Abramowitz-Stegun 7.1.26 erf (|abs err| < 1.5e-7)
__device__ __forceinline__ float erf_as(float x) {
    float ax = fabsf(x);
    float t  = __frcp_rn(1.f + 0.3275911f * ax);
    float y  = t * (0.254829592f + t * (-0.284496736f + t * (1.421413741f
             + t * (-1.453152027f + t * 1.061405429f))));
    float r  = 1.f - y * __expf(-ax * ax);
    return copysignf(r, x);
}

// half weight images, pperm2-permuted pairs (uint4 = 2 k-steps per lane)
__device__ uu g_wqkv[288 * 48];   // q-rows (0..95) pre-scaled by 24^-0.5
__device__ uu g_wproj[96 * 48];
__device__ uu g_w1[384 * 48];
__device__ uu g_w2[96 * 192];
__device__ float g_bqkv[288];
// bias+mask table, half2-packed, lane-contiguous: [v][h][n][lr*8 + nt]
__device__ uu g_sbias[4 * 4 * 64 * 32];

__global__ void swin_prep_kernel(const float* __restrict__ qkv_w,
                                 const float* __restrict__ proj_w,
                                 const float* __restrict__ fc1_w,
                                 const float* __restrict__ fc2_w,
                                 const float* __restrict__ qkv_b,
                                 const float* __restrict__ rpb)
{
    const float scale = 0.2041241452319315f;  // 24^-0.5
    int t = blockIdx.x * blockDim.x + threadIdx.x;
    int T = gridDim.x * blockDim.x;
    for (int i = t; i < 288 * 48; i += T) {
        int r = i / 48, p = i - r * 48;
        float s = (r < 96) ? scale : 1.f;
        g_wqkv[r * 48 + pperm2(p)] =
            packh2(__ldg(qkv_w + r * 96 + 2 * p) * s,
                   __ldg(qkv_w + r * 96 + 2 * p + 1) * s);
    }
    for (int i = t; i < 288; i += T)
        g_bqkv[i] = __ldg(qkv_b + i) * ((i < 96) ? scale : 1.f);
    for (int i = t; i < 96 * 48; i += T) {
        int r = i / 48, p = i - r * 48;
        g_wproj[r * 48 + pperm2(p)] =
            packh2(__ldg(proj_w + r * 96 + 2 * p), __ldg(proj_w + r * 96 + 2 * p + 1));
    }
    for (int i = t; i < 384 * 48; i += T) {
        int r = i / 48, p = i - r * 48;
        g_w1[r * 48 + pperm2(p)] =
            packh2(__ldg(fc1_w + r * 96 + 2 * p), __ldg(fc1_w + r * 96 + 2 * p + 1));
    }
    for (int i = t; i < 96 * 192; i += T) {
        int c = i / 192, p = i - c * 192;
        g_w2[c * 192 + pperm2(p)] =
            packh2(__ldg(fc2_w + c * 384 + 2 * p), __ldg(fc2_w + c * 384 + 2 * p + 1));
    }
    // bias+mask, half2 packed: word w = lr*8 + nt holds m pair (nt*8+2lr, +1)
    for (int i = t; i < 4 * 4 * 64 * 32; i += T) {
        int w  = i & 31;
        int lr = w >> 3, nt = w & 7;
        int n  = (i >> 5) & 63;
        int h  = (i >> 11) & 3;
        int v  = (i >> 13) & 3;
        int i1 = n >> 3, j1 = n & 7;
        float bv[2];
        #pragma unroll
        for (int par = 0; par < 2; par++) {
            int m  = nt * 8 + 2 * lr + par;
            int i2 = m >> 3, j2 = m & 7;
            int ridx = (i1 - i2 + 7) * 15 + (j1 - j2 + 7);
            float bias = __ldg(rpb + ridx * 4 + h);
            int rn = (v & 2) ? ((i1 < 4) ? 1 : 2) : 0;
            int cn = (v & 1) ? ((j1 < 4) ? 1 : 2) : 0;
            int rm = (v & 2) ? ((i2 < 4) ? 1 : 2) : 0;
            int cm = (v & 1) ? ((j2 < 4) ? 1 : 2) : 0;
            if ((rn * 3 + cn) != (rm * 3 + cm)) bias -= 100.f;
            bv[par] = bias;
        }
        g_sbias[i] = packh2(bv[0], bv[1]);
    }
}

// ---------------- fused kernel smem (word indices) ----------------
#define F_XT   0        // raw x fp32 [64][104] -> ys f16 [64][48]
#define F_XH   6656     // Xh f16 [64][48] -> AO -> hct (3072 words)
#define F_Q    9728     // Q f16 [4][64][16] (4096) -> hout fp32 [64][104]
#define F_K    13824    // K f16 [4][64][16] (4096)
#define F_VT   17920    // V^T f16 [2][96][16] (3072)
#define F_TOT  20992    // 83,968 bytes

__global__ void __launch_bounds__(256, 2) swin_fused_kernel(
    const float* __restrict__ x,
    const float* __restrict__ norm_w, const float* __restrict__ norm_b,
    const float* __restrict__ proj_b,
    const float* __restrict__ n2w, const float* __restrict__ n2b,
    const float* __restrict__ b1g, const float* __restrict__ b2g,
    float* __restrict__ out)
{
    extern __shared__ float sm[];
    float* xt   = sm + F_XT;
    float* hout = sm + F_Q;             // h = x + attn (overlays Q..K)

    uu* Xhu = (uu*)(sm + F_XH);
    uu* AOu = (uu*)(sm + F_XH);
    uu* Hcu = (uu*)(sm + F_XH);
    uu* Ysu = (uu*)(sm + F_XT);
    uu* Qu  = (uu*)(sm + F_Q);
    uu* Ku  = (uu*)(sm + F_K);
    uu* Vtu = (uu*)(sm + F_VT);

    const int tid  = threadIdx.x;
    const int lane = tid & 31;
    const int wid  = tid >> 5;            // 0..7
    const int lq   = lane >> 2;
    const int lr   = lane & 3;
    const int mh   = wid >> 2;            // 0..1 (m32 group)
    const int nq   = wid & 3;             // 0..3
    const int hh   = wid & 3;             // scores/AV head
    const int mq   = wid >> 2;            // scores/AV 32-row slice
    const int blk  = blockIdx.x;
    const int b    = blk >> 10;
    const int wh   = (blk >> 5) & 31;
    const int ww   = blk & 31;
    const int variant = ((wh == 31) ? 2 : 0) | ((ww == 31) ? 1 : 0);

    // zero Q/K pad slots (disjoint from QKV-epilogue writes; ordered by (3))
    for (int i = tid; i < 2048; i += 256) {
        int sl = 3 + 4 * (i & 3);
        int hd = (i >> 2) & 3;
        int r  = (i >> 4) & 63;
        uu* dst = (i & 1024) ? Ku : Qu;
        dst[hd * 1024 + r * 16 + sl] = 0;
    }

    const int xbase = b * 96 * 65536;

    // ---- gather + LN1 in registers (4 lanes per token), pos inlined ----
    {
        int p = tid >> 2, part = tid & 3;
        int pr = (wh * 8 + (p >> 3) + 4) & 255;
        int pc = (ww * 8 + (p & 7) + 4) & 255;
        const float* xp = x + xbase + pr * 256 + pc;
        float g[24];
        #pragma unroll
        for (int i = 0; i < 24; i++) g[i] = __ldg(xp + ((part * 24 + i) << 16));
        float s = 0.f, s2 = 0.f;
        #pragma unroll
        for (int i = 0; i < 24; i++) { s += g[i]; s2 += g[i] * g[i]; }
        #pragma unroll
        for (int o = 1; o < 4; o <<= 1) {
            s  += __shfl_xor_sync(0xffffffffu, s,  o);
            s2 += __shfl_xor_sync(0xffffffffu, s2, o);
        }
        float mu = s * (1.f / 96.f);
        float var = s2 * (1.f / 96.f) - mu * mu;
        float rs = rsqrtf(var + 1e-6f);
        float* xr = xt + p * 104 + part * 24;
        #pragma unroll
        for (int i = 0; i < 6; i++)
            *(float4*)(xr + 4 * i) = make_float4(g[4 * i], g[4 * i + 1],
                                                 g[4 * i + 2], g[4 * i + 3]);
        #pragma unroll
        for (int i = 0; i < 12; i++) {
            int c = part * 24 + 2 * i;
            float2 nw = __ldg((const float2*)norm_w + (c >> 1));
            float2 nb = __ldg((const float2*)norm_b + (c >> 1));
            Xhu[p * 48 + pperm2(part * 12 + i)] =
                packh2((g[2 * i] - mu) * rs * nw.x + nb.x,
                       (g[2 * i + 1] - mu) * rs * nw.y + nb.y);
        }
    }
    __syncthreads();                                   // (2)

    // -------- QKV: m32 x n72, 3 ks2 groups (2 k-steps each) --------
    {
        float acc[9][2][4];
        #pragma unroll
        for (int nt = 0; nt < 9; nt++)
            #pragma unroll
            for (int mt = 0; mt < 2; mt++)
                #pragma unroll
                for (int e = 0; e < 4; e++) acc[nt][mt][e] = 0.f;

        const uu* wb = g_wqkv + (nq * 72 + lq) * 48 + lr * 4;
        #pragma unroll
        for (int ks2 = 0; ks2 < 3; ks2++) {
            uu ae[2][4], ao[2][4];
            #pragma unroll
            for (int mt = 0; mt < 2; mt++) {
                uint4 lo = *(const uint4*)(Xhu + (mh * 32 + mt * 16 + lq) * 48
                                           + ks2 * 16 + lr * 4);
                uint4 hi = *(const uint4*)(Xhu + (mh * 32 + mt * 16 + lq + 8) * 48
                                           + ks2 * 16 + lr * 4);
                ae[mt][0] = lo.x; ae[mt][1] = hi.x; ae[mt][2] = lo.y; ae[mt][3] = hi.y;
                ao[mt][0] = lo.z; ao[mt][1] = hi.z; ao[mt][2] = lo.w; ao[mt][3] = hi.w;
            }
            #pragma unroll
            for (int nt = 0; nt < 9; nt++) {
                uint4 bw = __ldg((const uint4*)(wb + nt * 8 * 48 + ks2 * 16));
                #pragma unroll
                for (int mt = 0; mt < 2; mt++) {
                    mmaf16(acc[nt][mt], ae[mt], bw.x, bw.y);
                    mmaf16(acc[nt][mt], ao[mt], bw.z, bw.w);
                }
            }
        }
        #pragma unroll
        for (int nt = 0; nt < 9; nt++) {
            int j0 = nq * 72 + nt * 8;
            float bl = __ldg(g_bqkv + j0 + 2 * lr);
            float bh = __ldg(g_bqkv + j0 + 2 * lr + 1);
            #pragma unroll
            for (int mt = 0; mt < 2; mt++) {
                int row = mh * 32 + mt * 16 + lq;
                int col = j0 + 2 * lr;
                float v0 = acc[nt][mt][0] + bl;
                float v1 = acc[nt][mt][1] + bh;
                float v2 = acc[nt][mt][2] + bl;
                float v3 = acc[nt][mt][3] + bh;
                if (col < 192) {
                    uu* dst;
                    int cl = col;
                    if (col < 96) { dst = Qu; } else { dst = Ku; cl = col - 96; }
                    int head = cl / 24;
                    int q    = (cl - head * 24) >> 1;
                    int sl   = ((q & 3) << 2) | (((q >> 3) & 1) << 1) | ((q >> 2) & 1);
                    dst[head * 1024 + row * 16 + sl]       = packh2(v0, v1);
                    dst[head * 1024 + (row + 8) * 16 + sl] = packh2(v2, v3);
                } else {
                    int cc = col - 192;
                    #pragma unroll
                    for (int e = 0; e < 4; e++) {
                        float v = (e == 0) ? v0 : (e == 1) ? v1 : (e == 2) ? v2 : v3;
                        int n = row + ((e >> 1) << 3);
                        int c2 = cc + (e & 1);
                        int tp = n >> 1;
                        int g  = tp >> 4;
                        int q  = tp & 15;
                        int sl = ((q & 3) << 2) | (((q >> 3) & 1) << 1) | ((q >> 2) & 1);
                        ((__half*)(Vtu + g * 1536 + c2 * 16 + sl))[n & 1] =
                            __float2half_rn(v);
                    }
                }
            }
        }
    }
    __syncthreads();                                   // (3)

    // ---- Scores (m32 x 64): acc init from half2 g_sbias, softmax, AV ----
    {
        float acc[8][2][4];
        const uu* sb = g_sbias + (((variant * 4 + hh) * 64 + mq * 32 + lq) * 32)
                     + lr * 8;
        #pragma unroll
        for (int mt = 0; mt < 2; mt++) {
            const uint4* lo4 = (const uint4*)(sb + (mt * 16) * 32);
            const uint4* hi4 = (const uint4*)(sb + (mt * 16 + 8) * 32);
            #pragma unroll
            for (int q = 0; q < 2; q++) {
                uint4 L = __ldg(lo4 + q);
                uint4 H = __ldg(hi4 + q);
                float2 f;
                f = h2f2(L.x); acc[4*q+0][mt][0] = f.x; acc[4*q+0][mt][1] = f.y;
                f = h2f2(L.y); acc[4*q+1][mt][0] = f.x; acc[4*q+1][mt][1] = f.y;
                f = h2f2(L.z); acc[4*q+2][mt][0] = f.x; acc[4*q+2][mt][1] = f.y;
                f = h2f2(L.w); acc[4*q+3][mt][0] = f.x; acc[4*q+3][mt][1] = f.y;
                f = h2f2(H.x); acc[4*q+0][mt][2] = f.x; acc[4*q+0][mt][3] = f.y;
                f = h2f2(H.y); acc[4*q+1][mt][2] = f.x; acc[4*q+1][mt][3] = f.y;
                f = h2f2(H.z); acc[4*q+2][mt][2] = f.x; acc[4*q+2][mt][3] = f.y;
                f = h2f2(H.w); acc[4*q+3][mt][2] = f.x; acc[4*q+3][mt][3] = f.y;
            }
        }
        {
            uu ae[2][4], ao[2][4];
            #pragma unroll
            for (int mt = 0; mt < 2; mt++) {
                uint4 lo = *(const uint4*)(Qu + hh * 1024
                                           + (mq * 32 + mt * 16 + lq) * 16 + lr * 4);
                uint4 hi = *(const uint4*)(Qu + hh * 1024
                                           + (mq * 32 + mt * 16 + lq + 8) * 16 + lr * 4);
                ae[mt][0] = lo.x; ae[mt][1] = hi.x; ae[mt][2] = lo.y; ae[mt][3] = hi.y;
                ao[mt][0] = lo.z; ao[mt][1] = hi.z; ao[mt][2] = lo.w; ao[mt][3] = hi.w;
            }
            #pragma unroll
            for (int nt = 0; nt < 8; nt++) {
                uint4 kf = *(const uint4*)(Ku + hh * 1024 + (nt * 8 + lq) * 16 + lr * 4);
                #pragma unroll
                for (int mt = 0; mt < 2; mt++) {
                    mmaf16(acc[nt][mt], ae[mt], kf.x, kf.y);
                    mmaf16(acc[nt][mt], ao[mt], kf.z, kf.w);
                }
            }
        }
        // softmax (no max-subtract: |scores| small; mask -100 -> exp -> 0) + AV
        float fav[3][2][4];
        #pragma unroll
        for (int nt = 0; nt < 3; nt++)
            #pragma unroll
            for (int mt = 0; mt < 2; mt++)
                #pragma unroll
                for (int e = 0; e < 4; e++) fav[nt][mt][e] = 0.f;

        #pragma unroll
        for (int mt = 0; mt < 2; mt++) {
            float sm0 = 0.f, sm1 = 0.f;
            #pragma unroll
            for (int nt = 0; nt < 8; nt++) {
                acc[nt][mt][0] = __expf(acc[nt][mt][0]);
                acc[nt][mt][1] = __expf(acc[nt][mt][1]);
                acc[nt][mt][2] = __expf(acc[nt][mt][2]);
                acc[nt][mt][3] = __expf(acc[nt][mt][3]);
                sm0 += acc[nt][mt][0] + acc[nt][mt][1];
                sm1 += acc[nt][mt][2] + acc[nt][mt][3];
            }
            #pragma unroll
            for (int o = 1; o < 4; o <<= 1) {
                sm0 += __shfl_xor_sync(0xffffffffu, sm0, o);
                sm1 += __shfl_xor_sync(0xffffffffu, sm1, o);
            }
            float inv0 = __fdividef(1.f, sm0);
            float inv1 = __fdividef(1.f, sm1);
            #pragma unroll
            for (int g = 0; g < 2; g++) {
                uu a_e[4], a_o[4];
                a_e[0] = packh2(acc[4 * g][mt][0] * inv0,     acc[4 * g][mt][1] * inv0);
                a_e[1] = packh2(acc[4 * g][mt][2] * inv1,     acc[4 * g][mt][3] * inv1);
                a_e[2] = packh2(acc[4 * g + 1][mt][0] * inv0, acc[4 * g + 1][mt][1] * inv0);
                a_e[3] = packh2(acc[4 * g + 1][mt][2] * inv1, acc[4 * g + 1][mt][3] * inv1);
                a_o[0] = packh2(acc[4 * g + 2][mt][0] * inv0, acc[4 * g + 2][mt][1] * inv0);
                a_o[1] = packh2(acc[4 * g + 2][mt][2] * inv1, acc[4 * g + 2][mt][3] * inv1);
                a_o[2] = packh2(acc[4 * g + 3][mt][0] * inv0, acc[4 * g + 3][mt][1] * inv0);
                a_o[3] = packh2(acc[4 * g + 3][mt][2] * inv1, acc[4 * g + 3][mt][3] * inv1);
                #pragma unroll
                for (int nt = 0; nt < 3; nt++) {
                    uint4 vf = *(const uint4*)(Vtu + g * 1536
                                               + (hh * 24 + nt * 8 + lq) * 16 + lr * 4);
                    mmaf16(fav[nt][mt], a_e, vf.x, vf.y);
                    mmaf16(fav[nt][mt], a_o, vf.z, vf.w);
                }
            }
        }
        // AO overlay of Xh safe without barrier (Xh last read before (3))
        #pragma unroll
        for (int nt = 0; nt < 3; nt++)
            #pragma unroll
            for (int mt = 0; mt < 2; mt++) {
                int n0 = mq * 32 + mt * 16 + lq;
                int cp = hh * 12 + nt * 4 + lr;
                AOu[n0 * 48 + pperm2(cp)]       = packh2(fav[nt][mt][0], fav[nt][mt][1]);
                AOu[(n0 + 8) * 48 + pperm2(cp)] = packh2(fav[nt][mt][2], fav[nt][mt][3]);
            }
    }
    __syncthreads();                                   // (5)

    // ------- Proj (m32 x n24, 3 ks2) + residual(xt) -> hout -------
    {
        float acc[3][2][4];
        #pragma unroll
        for (int nt = 0; nt < 3; nt++)
            #pragma unroll
            for (int mt = 0; mt < 2; mt++)
                #pragma unroll
                for (int e = 0; e < 4; e++) acc[nt][mt][e] = 0.f;

        const uu* wb = g_wproj + (nq * 24 + lq) * 48 + lr * 4;
        #pragma unroll
        for (int ks2 = 0; ks2 < 3; ks2++) {
            uu ae[2][4], ao[2][4];
            #pragma unroll
            for (int mt = 0; mt < 2; mt++) {
                uint4 lo = *(const uint4*)(AOu + (mh * 32 + mt * 16 + lq) * 48
                                           + ks2 * 16 + lr * 4);
                uint4 hi = *(const uint4*)(AOu + (mh * 32 + mt * 16 + lq + 8) * 48
                                           + ks2 * 16 + lr * 4);
                ae[mt][0] = lo.x; ae[mt][1] = hi.x; ae[mt][2] = lo.y; ae[mt][3] = hi.y;
                ao[mt][0] = lo.z; ao[mt][1] = hi.z; ao[mt][2] = lo.w; ao[mt][3] = hi.w;
            }
            #pragma unroll
            for (int nt = 0; nt < 3; nt++) {
                uint4 bw = __ldg((const uint4*)(wb + nt * 8 * 48 + ks2 * 16));
                #pragma unroll
                for (int mt = 0; mt < 2; mt++) {
                    mmaf16(acc[nt][mt], ae[mt], bw.x, bw.y);
                    mmaf16(acc[nt][mt], ao[mt], bw.z, bw.w);
                }
            }
        }
        #pragma unroll
        for (int nt = 0; nt < 3; nt++) {
            int j0 = nq * 24 + nt * 8;
            float bl = __ldg(proj_b + j0 + 2 * lr);
            float bh = __ldg(proj_b + j0 + 2 * lr + 1);
            #pragma unroll
            for (int mt = 0; mt < 2; mt++)
                #pragma unroll
                for (int e = 0; e < 4; e++) {
                    int n = mh * 32 + mt * 16 + lq + ((e >> 1) << 3);
                    int j = j0 + 2 * lr + (e & 1);
                    hout[n * 104 + j] = acc[nt][mt][e] + ((e & 1) ? bh : bl)
                                      + xt[n * 104 + j];
                }
        }
    }
    __syncthreads();                                   // (6)

    // ---- LN2 from hout -> ys f16 (overlays xt region) ----
    {
        int p = tid >> 2, part = tid & 3;
        float g[24];
        const float* hp = hout + p * 104 + part * 24;
        #pragma unroll
        for (int i = 0; i < 6; i++) {
            float4 v = *(const float4*)(hp + 4 * i);
            g[4 * i] = v.x; g[4 * i + 1] = v.y; g[4 * i + 2] = v.z; g[4 * i + 3] = v.w;
        }
        float s = 0.f, s2 = 0.f;
        #pragma unroll
        for (int i = 0; i < 24; i++) { s += g[i]; s2 += g[i] * g[i]; }
        #pragma unroll
        for (int o = 1; o < 4; o <<= 1) {
            s  += __shfl_xor_sync(0xffffffffu, s,  o);
            s2 += __shfl_xor_sync(0xffffffffu, s2, o);
        }
        float mu = s * (1.f / 96.f);
        float var = s2 * (1.f / 96.f) - mu * mu;
        float rs = rsqrtf(var + 1e-6f);
        #pragma unroll
        for (int i = 0; i < 12; i++) {
            int c = part * 24 + 2 * i;
            float2 nw = __ldg((const float2*)n2w + (c >> 1));
            float2 nb = __ldg((const float2*)n2b + (c >> 1));
            Ysu[p * 48 + pperm2(part * 12 + i)] =
                packh2((g[2 * i] - mu) * rs * nw.x + nb.x,
                       (g[2 * i + 1] - mu) * rs * nw.y + nb.y);
        }
    }
    __syncthreads();                                   // (7)

    // ---- MLP: Ys A-fragments held in registers across all 4 quarters ----
    uu yse[3][2][4], yso[3][2][4];
    #pragma unroll
    for (int ks2 = 0; ks2 < 3; ks2++)
        #pragma unroll
        for (int mt = 0; mt < 2; mt++) {
            uint4 lo = *(const uint4*)(Ysu + (mh * 32 + mt * 16 + lq) * 48
                                       + ks2 * 16 + lr * 4);
            uint4 hi = *(const uint4*)(Ysu + (mh * 32 + mt * 16 + lq + 8) * 48
                                       + ks2 * 16 + lr * 4);
            yse[ks2][mt][0] = lo.x; yse[ks2][mt][1] = hi.x;
            yse[ks2][mt][2] = lo.y; yse[ks2][mt][3] = hi.y;
            yso[ks2][mt][0] = lo.z; yso[ks2][mt][1] = hi.z;
            yso[ks2][mt][2] = lo.w; yso[ks2][mt][3] = hi.w;
        }

    float acc2[3][2][4];
    #pragma unroll
    for (int nt = 0; nt < 3; nt++)
        #pragma unroll
        for (int mt = 0; mt < 2; mt++)
            #pragma unroll
            for (int e = 0; e < 4; e++) acc2[nt][mt][e] = 0.f;

    for (int ng = 0; ng < 4; ng++) {
        {
            float acc1[3][2][4];
            #pragma unroll
            for (int nt = 0; nt < 3; nt++)
                #pragma unroll
                for (int mt = 0; mt < 2; mt++)
                    #pragma unroll
                    for (int e = 0; e < 4; e++) acc1[nt][mt][e] = 0.f;

            const uu* wb = g_w1 + (ng * 96 + nq * 24 + lq) * 48 + lr * 4;
            #pragma unroll
            for (int ks2 = 0; ks2 < 3; ks2++) {
                #pragma unroll
                for (int nt = 0; nt < 3; nt++) {
                    uint4 bw = __ldg((const uint4*)(wb + nt * 8 * 48 + ks2 * 16));
                    #pragma unroll
                    for (int mt = 0; mt < 2; mt++) {
                        mmaf16(acc1[nt][mt], yse[ks2][mt], bw.x, bw.y);
                        mmaf16(acc1[nt][mt], yso[ks2][mt], bw.z, bw.w);
                    }
                }
            }
            #pragma unroll
            for (int nt = 0; nt < 3; nt++) {
                int jl = nq * 24 + nt * 8;
                float bl = __ldg(b1g + ng * 96 + jl + 2 * lr);
                float bh = __ldg(b1g + ng * 96 + jl + 2 * lr + 1);
                int pl = (jl >> 1) + lr;               // local hidden pair 0..47
                #pragma unroll
                for (int mt = 0; mt < 2; mt++) {
                    int p0r = mh * 32 + mt * 16 + lq;
                    float v0 = acc1[nt][mt][0] + bl;
                    float v1 = acc1[nt][mt][1] + bh;
                    float v2 = acc1[nt][mt][2] + bl;
                    float v3 = acc1[nt][mt][3] + bh;
                    v0 = 0.5f * v0 * (1.f + erf_as(v0 * 0.7071067811865475f));
                    v1 = 0.5f * v1 * (1.f + erf_as(v1 * 0.7071067811865475f));
                    v2 = 0.5f * v2 * (1.f + erf_as(v2 * 0.7071067811865475f));
                    v3 = 0.5f * v3 * (1.f + erf_as(v3 * 0.7071067811865475f));
                    Hcu[p0r * 48 + pperm2(pl)]       = packh2(v0, v1);
                    Hcu[(p0r + 8) * 48 + pperm2(pl)] = packh2(v2, v3);
                }
            }
        }
        __syncthreads();                               // hct quarter ready

        const uu* wb2 = g_w2 + (nq * 24 + lq) * 192 + ng * 48 + lr * 4;
        #pragma unroll
        for (int ks2 = 0; ks2 < 3; ks2++) {
            uu ae[2][4], ao[2][4];
            #pragma unroll
            for (int mt = 0; mt < 2; mt++) {
                uint4 lo = *(const uint4*)(Hcu + (mh * 32 + mt * 16 + lq) * 48
                                           + ks2 * 16 + lr * 4);
                uint4 hi = *(const uint4*)(Hcu + (mh * 32 + mt * 16 + lq + 8) * 48
                                           + ks2 * 16 + lr * 4);
                ae[mt][0] = lo.x; ae[mt][1] = hi.x; ae[mt][2] = lo.y; ae[mt][3] = hi.y;
                ao[mt][0] = lo.z; ao[mt][1] = hi.z; ao[mt][2] = lo.w; ao[mt][3] = hi.w;
            }
            #pragma unroll
            for (int nt = 0; nt < 3; nt++) {
                uint4 bw = __ldg((const uint4*)(wb2 + nt * 8 * 192 + ks2 * 16));
                #pragma unroll
                for (int mt = 0; mt < 2; mt++) {
                    mmaf16(acc2[nt][mt], ae[mt], bw.x, bw.y);
                    mmaf16(acc2[nt][mt], ao[mt], bw.z, bw.w);
                }
            }
        }
        if (ng < 3) __syncthreads();                   // WAR on Hcu (skip last)
    }

    // epilogue: bias + residual (hout) -> DIRECT gmem store (32B sectors)
    #pragma unroll
    for (int nt = 0; nt < 3; nt++) {
        int c0 = nq * 24 + nt * 8;
        float bl = __ldg(b2g + c0 + 2 * lr);
        float bh = __ldg(b2g + c0 + 2 * lr + 1);
        #pragma unroll
        for (int mt = 0; mt < 2; mt++)
            #pragma unroll
            for (int e = 0; e < 4; e++) {
                int p = mh * 32 + mt * 16 + lq + ((e >> 1) << 3);
                int c = c0 + 2 * lr + (e & 1);
                float v = acc2[nt][mt][e] + ((e & 1) ? bh : bl)
                        + hout[p * 104 + c];
                int pr = (wh * 8 + (p >> 3) + 4) & 255;
                int pc = (ww * 8 + (p & 7) + 4) & 255;
                out[((size_t)(b * 96 + c) << 16) + pr * 256 + pc] = v;
            }
    }
}

extern "C" void kernel_launch(void* const* d_in, const int* in_sizes, int n_in,
                              void* d_out, int out_size)
{
    const float* x      = (const float*)d_in[0];
    const float* norm_w = (const float*)d_in[1];
    const float* norm_b = (const float*)d_in[2];
    const float* qkv_w  = (const float*)d_in[3];
    const float* qkv_b  = (const float*)d_in[4];
    const float* proj_w = (const float*)d_in[5];
    const float* proj_b = (const float*)d_in[6];
    const float* rpb    = (const float*)d_in[7];
    const float* n2w    = (const float*)d_in[8];
    const float* n2b    = (const float*)d_in[9];
    const float* fc1_w  = (const float*)d_in[10];
    const float* fc1_b  = (const float*)d_in[11];
    const float* fc2_w  = (const float*)d_in[12];
    const float* fc2_b  = (const float*)d_in[13];
    float* out = (float*)d_out;

    cudaFuncSetAttribute(swin_fused_kernel, cudaFuncAttributeMaxDynamicSharedMemorySize,
                         F_TOT * 4);

    swin_prep_kernel<<<112, 256>>>(qkv_w, proj_w, fc1_w, fc2_w, qkv_b, rpb);
    swin_fused_kernel<<<4096, 256, F_TOT * 4>>>(
        x, norm_w, norm_b, proj_b, n2w, n2b, fc1_b, fc2_b, out);
}